// round 15
// baseline (speedup 1.0000x reference)
#include <cuda_runtime.h>
#include <cuda_fp16.h>
#include <cstdint>

static constexpr int BATCH = 8192;
static constexpr int SEQ   = 658;
static constexpr int INP   = 7;
static constexpr int D1    = 1024;
static constexpr int D2    = 512;
static constexpr int D3    = 128;
static constexpr int KP_T  = 704;   // SEQ padded to multiple of 64
static constexpr int M4P   = 768;   // L4 M (=SEQ) padded to multiple of 128

// ---------------- device scratch ----------------
__device__ __align__(16) float  g_xw[(size_t)SEQ * BATCH];    // [t][b]
__device__ __align__(16) __half g_hs_h[(size_t)SEQ * BATCH];  // [t][b] fp16
// fp16 activations, batch-major [b][k]
__device__ __align__(16) __half g_hsT[(size_t)BATCH * KP_T];
__device__ __align__(16) __half g_a1[(size_t)BATCH * D1];
__device__ __align__(16) __half g_a2[(size_t)BATCH * D2];
__device__ __align__(16) __half g_a3[(size_t)BATCH * D3];
// fp16 split weights, K-major [m][k], zero-padded
__device__ __align__(16) __half g_w1_hi[(size_t)D1 * KP_T];
__device__ __align__(16) __half g_w1_lo[(size_t)D1 * KP_T];
__device__ __align__(16) __half g_w2_hi[(size_t)D2 * D1];
__device__ __align__(16) __half g_w2_lo[(size_t)D2 * D1];
__device__ __align__(16) __half g_w3_hi[(size_t)D3 * D2];
__device__ __align__(16) __half g_w3_lo[(size_t)D3 * D2];
__device__ __align__(16) __half g_w4_hi[(size_t)M4P * D3];
__device__ __align__(16) __half g_w4_lo[(size_t)M4P * D3];

// ---------------- helpers ----------------
__device__ __forceinline__ uint32_t smem_u32(const void* p) {
    uint32_t a;
    asm("{ .reg .u64 t; cvta.to.shared.u64 t, %1; cvt.u32.u64 %0, t; }" : "=r"(a) : "l"(p));
    return a;
}
#define CP_ASYNC16(s, g) \
    asm volatile("cp.async.cg.shared.global [%0], [%1], 16;" :: "r"(s), "l"(g) : "memory")
#define CP_COMMIT() asm volatile("cp.async.commit_group;" ::: "memory")
#define CP_WAIT1()  asm volatile("cp.async.wait_group 1;" ::: "memory")

#define LDSM4(R0, R1, R2, R3, ADDR) \
    asm volatile("ldmatrix.sync.aligned.m8n8.x4.shared.b16 {%0,%1,%2,%3}, [%4];" \
                 : "=r"(R0), "=r"(R1), "=r"(R2), "=r"(R3) : "r"(ADDR))

#define MMA_F16(D, A, B0, B1) \
    asm volatile("mma.sync.aligned.m16n8k16.row.col.f32.f16.f16.f32 " \
                 "{%0,%1,%2,%3}, {%4,%5,%6,%7}, {%8,%9}, {%0,%1,%2,%3};" \
                 : "+f"((D)[0]), "+f"((D)[1]), "+f"((D)[2]), "+f"((D)[3]) \
                 : "r"((A)[0]), "r"((A)[1]), "r"((A)[2]), "r"((A)[3]), \
                   "r"(B0), "r"(B1))

// ---------------------------------------------------------------------------
// Kernel 1: input projection. xw[t][b] = dot(x[b,t,:], W_ih) + b_ih + b_hh
// ---------------------------------------------------------------------------
__global__ __launch_bounds__(256)
void xw_kernel(const float* __restrict__ x,
               const float* __restrict__ W_ih,
               const float* __restrict__ b_ih,
               const float* __restrict__ b_hh,
               float* __restrict__ xw) {
    __shared__ float sx[32 * 225];
    const int b0 = blockIdx.x * 32;
    const int t0 = blockIdx.y * 32;
    const int tid = threadIdx.x;

    for (int e = tid; e < 32 * 224; e += 256) {
        int bb = e / 224, rem = e % 224;
        int t = t0 + rem / 7;
        float v = 0.f;
        if (t < SEQ)
            v = x[((size_t)(b0 + bb) * SEQ + t0) * INP + rem];
        sx[bb * 225 + rem] = v;
    }
    __syncthreads();

    const float w0 = W_ih[0], w1 = W_ih[1], w2 = W_ih[2], w3 = W_ih[3];
    const float w4 = W_ih[4], w5 = W_ih[5], w6 = W_ih[6];
    const float bias = b_ih[0] + b_hh[0];

    for (int e = tid; e < 1024; e += 256) {
        int bb = e % 32, tt = e / 32;
        int t = t0 + tt;
        if (t < SEQ) {
            const float* p = &sx[bb * 225 + tt * 7];
            float s = bias;
            s = fmaf(p[0], w0, s); s = fmaf(p[1], w1, s);
            s = fmaf(p[2], w2, s); s = fmaf(p[3], w3, s);
            s = fmaf(p[4], w4, s); s = fmaf(p[5], w5, s);
            s = fmaf(p[6], w6, s);
            xw[(size_t)t * BATCH + (b0 + bb)] = s;
        }
    }
}

// ---------------------------------------------------------------------------
// Kernel 2: RNN scan (H=1 scalar recurrence), writes fp16 hs
// ---------------------------------------------------------------------------
__global__ __launch_bounds__(128)
void rnn_kernel(const float* __restrict__ xw,
                const float* __restrict__ h0,
                const float* __restrict__ W_hh,
                __half* __restrict__ hs,
                float* __restrict__ hid_out,
                int write_hidden) {
    int b = blockIdx.x * blockDim.x + threadIdx.x;
    if (b >= BATCH) return;
    float h = h0[b];
    const float w = W_hh[0];
    for (int t = 0; t < SEQ; t++) {
        float u = fmaf(w, h, xw[(size_t)t * BATCH + b]);
        float e = __expf(2.f * u);
        h = fmaf(-2.f, __fdividef(1.f, e + 1.f), 1.f);
        hs[(size_t)t * BATCH + b] = __float2half(h);
    }
    if (write_hidden) hid_out[b] = h;
}

// ---------------------------------------------------------------------------
// Kernel 3: transpose hs [t][b] (fp16) -> [b][KP_T] (fp16, zero-padded)
// Consistent 64t x 64b tile through s[64 b][65 t-padded].
// ---------------------------------------------------------------------------
__global__ __launch_bounds__(256)
void transpose_kernel(const __half* __restrict__ hs, __half* __restrict__ hsT) {
    __shared__ __half s[64][65];   // [b][t]
    const int b0 = blockIdx.x * 64, t0 = blockIdx.y * 64;
    const int lx = threadIdx.x & 31, ly = threadIdx.x >> 5;  // ly 0..7
#pragma unroll
    for (int r = 0; r < 8; r++) {
        const int tt = ly + r * 8;          // 0..63
        const int t = t0 + tt;
        __half2 v = __float2half2_rn(0.f);
        if (t < SEQ)
            v = *reinterpret_cast<const __half2*>(hs + (size_t)t * BATCH + b0 + 2 * lx);
        s[2 * lx][tt]     = __low2half(v);
        s[2 * lx + 1][tt] = __high2half(v);
    }
    __syncthreads();
#pragma unroll
    for (int r = 0; r < 8; r++) {
        const int brow = ly + r * 8;        // 0..63
        __half2 v = __halves2half2(s[brow][2 * lx], s[brow][2 * lx + 1]);
        *reinterpret_cast<__half2*>(hsT + (size_t)(b0 + brow) * KP_T + t0 + 2 * lx) = v;
    }
}

// ---------------------------------------------------------------------------
// Kernel 4: all weight splits in ONE launch. 4096 elems per block.
// ---------------------------------------------------------------------------
__device__ __forceinline__ void split_seg(const float* __restrict__ src,
                                          int Mv, int Kv, int Kp,
                                          __half* __restrict__ hi,
                                          __half* __restrict__ lo, int blk) {
    const int base = blk * 4096;
#pragma unroll
    for (int i = 0; i < 16; i++) {
        int idx = base + threadIdx.x + i * 256;
        int r = idx / Kp, c = idx % Kp;
        float v = (r < Mv && c < Kv) ? src[(size_t)r * Kv + c] : 0.f;
        __half h = __float2half(v);
        hi[idx] = h;
        lo[idx] = __float2half(v - __half2float(h));
    }
}

static constexpr int SPLIT_B1 = (D1 * KP_T) / 4096;  // 176
static constexpr int SPLIT_B2 = (D2 * D1) / 4096;    // 128
static constexpr int SPLIT_B3 = (D3 * D2) / 4096;    // 16
static constexpr int SPLIT_B4 = (M4P * D3) / 4096;   // 24
static constexpr int SPLIT_BLOCKS = SPLIT_B1 + SPLIT_B2 + SPLIT_B3 + SPLIT_B4;

__global__ __launch_bounds__(256)
void weight_split_kernel(const float* __restrict__ w1, const float* __restrict__ w2,
                         const float* __restrict__ w3, const float* __restrict__ w4,
                         __half* w1h, __half* w1l, __half* w2h, __half* w2l,
                         __half* w3h, __half* w3l, __half* w4h, __half* w4l) {
    int blk = blockIdx.x;
    if (blk < SPLIT_B1) { split_seg(w1, D1, SEQ, KP_T, w1h, w1l, blk); return; }
    blk -= SPLIT_B1;
    if (blk < SPLIT_B2) { split_seg(w2, D2, D1, D1, w2h, w2l, blk); return; }
    blk -= SPLIT_B2;
    if (blk < SPLIT_B3) { split_seg(w3, D3, D2, D2, w3h, w3l, blk); return; }
    blk -= SPLIT_B3;
    split_seg(w4, SEQ, D3, D3, w4h, w4l, blk);
}

// ---------------------------------------------------------------------------
// Kernel 5: HMMA fp16 GEMM, weights hi/lo 2-pass, 3-stage cp.async pipeline.
//   C[m][n] = sum_k (Ahi+Alo)[m][k] * B[n][k] + bias[m]
//   BM = WM*32, BN = 128. 256 threads, warp tile 32m x (NI*8)n.
//   SMEM row stride 40 halves (80B) -> conflict-free ldmatrix.
// ---------------------------------------------------------------------------
template <int WM, int NI, bool RELU, bool HALF_OUT>
__global__ __launch_bounds__(256)
void mma_gemm_kernel(const __half* __restrict__ Ahi, const __half* __restrict__ Alo,
                     const __half* __restrict__ B,
                     const float* __restrict__ bias,
                     __half* __restrict__ Ch, float* __restrict__ Cf,
                     int Kpad, int Dout, int Mvalid) {
    constexpr int BM = WM * 32;
    constexpr int WN = 8 / WM;
    static_assert(WN * NI * 8 == 128, "BN must be 128");
    constexpr uint32_t T_AL  = BM * 80;
    constexpr uint32_t T_B   = 2 * BM * 80;
    constexpr uint32_t STAGE = (2 * BM + 128) * 80;

    extern __shared__ __align__(16) char smem[];
    const int tid  = threadIdx.x;
    const int lane = tid & 31;
    const int wid  = tid >> 5;
    const int m0 = blockIdx.y * BM;
    const int n0 = blockIdx.x * 128;
    const int m_base = (wid % WM) * 32;
    const int n_base = (wid / WM) * (NI * 8);
    const uint32_t sbase = smem_u32(smem);

    const __half* gAh = Ahi + (size_t)m0 * Kpad;
    const __half* gAl = Alo + (size_t)m0 * Kpad;
    const __half* gB  = B   + (size_t)n0 * Kpad;

    float acc[2][NI][4];
#pragma unroll
    for (int mi = 0; mi < 2; mi++)
#pragma unroll
        for (int ni = 0; ni < NI; ni++)
#pragma unroll
            for (int v = 0; v < 4; v++) acc[mi][ni][v] = 0.f;

    const int stages = Kpad >> 5;

    auto load_stage = [&](int s, int buf) {
        const uint32_t sb = sbase + buf * STAGE;
        const int kofs = s << 5;
#pragma unroll
        for (int c = tid; c < BM * 4; c += 256) {
            const int rr = c >> 2, cc = c & 3;
            const uint32_t so = rr * 80 + cc * 16;
            const size_t go = (size_t)rr * Kpad + kofs + cc * 8;
            CP_ASYNC16(sb + so, gAh + go);
            CP_ASYNC16(sb + T_AL + so, gAl + go);
        }
#pragma unroll
        for (int c = tid; c < 512; c += 256) {
            const int rr = c >> 2, cc = c & 3;
            const uint32_t so = rr * 80 + cc * 16;
            const size_t go = (size_t)rr * Kpad + kofs + cc * 8;
            CP_ASYNC16(sb + T_B + so, gB + go);
        }
    };

    // 3-stage pipeline prologue (all layer K's give stages >= 4)
    load_stage(0, 0); CP_COMMIT();
    load_stage(1, 1); CP_COMMIT();

    for (int s = 0; s < stages; s++) {
        CP_WAIT1();          // stage s landed (s+1 may still be in flight)
        __syncthreads();     // also: all threads done computing stage s-1
        if (s + 2 < stages) { load_stage(s + 2, (s + 2) % 3); CP_COMMIT(); }
        const uint32_t sb = sbase + (s % 3) * STAGE;

#pragma unroll
        for (int step = 0; step < 2; step++) {
            const uint32_t kb = step * 32;
            uint32_t ah[2][4], al[2][4], b[NI][2];
            const uint32_t arow = (uint32_t)(m_base + (lane & 15)) * 80 + kb + (lane >> 4) * 16;
#pragma unroll
            for (int mi = 0; mi < 2; mi++) {
                const uint32_t ad = sb + arow + mi * (16 * 80);
                LDSM4(ah[mi][0], ah[mi][1], ah[mi][2], ah[mi][3], ad);
                LDSM4(al[mi][0], al[mi][1], al[mi][2], al[mi][3], ad + T_AL);
            }
            const uint32_t brow = (uint32_t)(n_base + (lane & 15)) * 80 + kb + (lane >> 4) * 16;
#pragma unroll
            for (int g = 0; g < NI / 2; g++) {
                uint32_t t0, t1, t2, t3;
                LDSM4(t0, t1, t2, t3, sb + T_B + brow + g * (16 * 80));
                b[2 * g][0] = t0; b[2 * g][1] = t2;
                b[2 * g + 1][0] = t1; b[2 * g + 1][1] = t3;
            }
            // pass 1: A_hi * B
#pragma unroll
            for (int mi = 0; mi < 2; mi++)
#pragma unroll
                for (int ni = 0; ni < NI; ni++)
                    MMA_F16(acc[mi][ni], ah[mi], b[ni][0], b[ni][1]);
            // pass 2: A_lo * B
#pragma unroll
            for (int mi = 0; mi < 2; mi++)
#pragma unroll
                for (int ni = 0; ni < NI; ni++)
                    MMA_F16(acc[mi][ni], al[mi], b[ni][0], b[ni][1]);
        }
    }

    // epilogue
    const int erow = lane >> 2;
    const int ecol = (lane & 3) * 2;
#pragma unroll
    for (int mi = 0; mi < 2; mi++) {
        const int mA = m0 + m_base + mi * 16 + erow;
        const int mB = mA + 8;
        const bool vA = mA < Mvalid, vB = mB < Mvalid;
        const float bA = vA ? bias[mA] : 0.f;
        const float bB = vB ? bias[mB] : 0.f;
#pragma unroll
        for (int ni = 0; ni < NI; ni++) {
            const int n = n0 + n_base + ni * 8 + ecol;
            float v00 = acc[mi][ni][0] + bA;
            float v01 = acc[mi][ni][1] + bA;
            float v10 = acc[mi][ni][2] + bB;
            float v11 = acc[mi][ni][3] + bB;
            if (RELU) {
                v00 = fmaxf(v00, 0.f); v01 = fmaxf(v01, 0.f);
                v10 = fmaxf(v10, 0.f); v11 = fmaxf(v11, 0.f);
            }
            if constexpr (HALF_OUT) {
                if (vA) {
                    Ch[(size_t)n * Dout + mA] = __float2half(v00);
                    Ch[(size_t)(n + 1) * Dout + mA] = __float2half(v01);
                }
                if (vB) {
                    Ch[(size_t)n * Dout + mB] = __float2half(v10);
                    Ch[(size_t)(n + 1) * Dout + mB] = __float2half(v11);
                }
            } else {
                if (vA) {
                    Cf[(size_t)n * Dout + mA] = v00;
                    Cf[(size_t)(n + 1) * Dout + mA] = v01;
                }
                if (vB) {
                    Cf[(size_t)n * Dout + mB] = v10;
                    Cf[(size_t)(n + 1) * Dout + mB] = v11;
                }
            }
        }
    }
}

// SMEM sizes per config (3 stages, Ahi+Alo+B tiles)
static constexpr int SMEM_A = 3 * (2 * 128 + 128) * 80;  // WM=4: 92160
static constexpr int SMEM_B = 3 * (2 * 64 + 128) * 80;   // WM=2: 61440

// ---------------------------------------------------------------------------
// Launch
// ---------------------------------------------------------------------------
extern "C" void kernel_launch(void* const* d_in, const int* in_sizes, int n_in,
                              void* d_out, int out_size) {
    const float* x    = (const float*)d_in[0];
    const float* h0   = (const float*)d_in[1];
    const float* W_ih = (const float*)d_in[2];
    const float* W_hh = (const float*)d_in[3];
    const float* b_ih = (const float*)d_in[4];
    const float* b_hh = (const float*)d_in[5];
    const float* w1   = (const float*)d_in[6];
    const float* b1   = (const float*)d_in[7];
    const float* w2   = (const float*)d_in[8];
    const float* b2   = (const float*)d_in[9];
    const float* w3   = (const float*)d_in[10];
    const float* b3   = (const float*)d_in[11];
    const float* w4   = (const float*)d_in[12];
    const float* b4   = (const float*)d_in[13];
    float* out = (float*)d_out;

    float *p_xw;
    __half *p_hs, *hsT, *a1, *a2, *a3;
    __half *w1h, *w1l, *w2h, *w2l, *w3h, *w3l, *w4h, *w4l;
    cudaGetSymbolAddress((void**)&p_xw, g_xw);
    cudaGetSymbolAddress((void**)&p_hs, g_hs_h);
    cudaGetSymbolAddress((void**)&hsT, g_hsT);
    cudaGetSymbolAddress((void**)&a1, g_a1);
    cudaGetSymbolAddress((void**)&a2, g_a2);
    cudaGetSymbolAddress((void**)&a3, g_a3);
    cudaGetSymbolAddress((void**)&w1h, g_w1_hi);
    cudaGetSymbolAddress((void**)&w1l, g_w1_lo);
    cudaGetSymbolAddress((void**)&w2h, g_w2_hi);
    cudaGetSymbolAddress((void**)&w2l, g_w2_lo);
    cudaGetSymbolAddress((void**)&w3h, g_w3_hi);
    cudaGetSymbolAddress((void**)&w3l, g_w3_lo);
    cudaGetSymbolAddress((void**)&w4h, g_w4_hi);
    cudaGetSymbolAddress((void**)&w4l, g_w4_lo);

    cudaFuncSetAttribute(mma_gemm_kernel<4, 8, true, true>,
                         cudaFuncAttributeMaxDynamicSharedMemorySize, SMEM_A);
    cudaFuncSetAttribute(mma_gemm_kernel<2, 4, true, true>,
                         cudaFuncAttributeMaxDynamicSharedMemorySize, SMEM_B);
    cudaFuncSetAttribute(mma_gemm_kernel<4, 8, false, false>,
                         cudaFuncAttributeMaxDynamicSharedMemorySize, SMEM_A);

    const size_t out_elems = (size_t)BATCH * SEQ;
    const int write_hidden = ((size_t)out_size >= out_elems + BATCH) ? 1 : 0;
    float* hid_out = out + out_elems;

    // Weight conversion: single launch
    weight_split_kernel<<<SPLIT_BLOCKS, 256>>>(w1, w2, w3, w4,
                                               w1h, w1l, w2h, w2l,
                                               w3h, w3l, w4h, w4l);

    // Input projection -> g_xw [t][b]
    {
        dim3 grid(BATCH / 32, (SEQ + 31) / 32);
        xw_kernel<<<grid, 256>>>(x, W_ih, b_ih, b_hh, p_xw);
    }
    // RNN scan -> fp16 hs [t][b], hidden tail fp32
    rnn_kernel<<<BATCH / 128, 128>>>(p_xw, h0, W_hh, p_hs, hid_out, write_hidden);

    // Transpose -> hsT [b][KP_T]
    {
        dim3 grid(BATCH / 64, KP_T / 64);
        transpose_kernel<<<grid, 256>>>(p_hs, hsT);
    }

    // L1: a1[b][D1] = relu(w1 . hs + b1)
    {
        dim3 grid(BATCH / 128, D1 / 128);
        mma_gemm_kernel<4, 8, true, true><<<grid, 256, SMEM_A>>>(
            w1h, w1l, hsT, b1, a1, nullptr, KP_T, D1, D1);
    }
    // L2: a2[b][D2] = relu(w2 . a1 + b2)
    {
        dim3 grid(BATCH / 128, D2 / 128);
        mma_gemm_kernel<4, 8, true, true><<<grid, 256, SMEM_A>>>(
            w2h, w2l, a1, b2, a2, nullptr, D1, D2, D2);
    }
    // L3: a3[b][D3] = relu(w3 . a2 + b3)   (BM=64 config -> 128 CTAs)
    {
        dim3 grid(BATCH / 128, D3 / 64);
        mma_gemm_kernel<2, 4, true, true><<<grid, 256, SMEM_B>>>(
            w3h, w3l, a2, b3, a3, nullptr, D2, D3, D3);
    }
    // L4: out[b][t] = w4 . a3 + b4  (fp32 out, m = t, guard m < SEQ)
    {
        dim3 grid(BATCH / 128, M4P / 128);
        mma_gemm_kernel<4, 8, false, false><<<grid, 256, SMEM_A>>>(
            w4h, w4l, a3, b4, nullptr, out, D3, SEQ, SEQ);
    }
}

// round 16
// speedup vs baseline: 1.0071x; 1.0071x over previous
#include <cuda_runtime.h>
#include <cuda_fp16.h>
#include <cstdint>

static constexpr int BATCH = 8192;
static constexpr int SEQ   = 658;
static constexpr int INP   = 7;
static constexpr int D1    = 1024;
static constexpr int D2    = 512;
static constexpr int D3    = 128;
static constexpr int KP_T  = 704;   // SEQ padded to multiple of 64
static constexpr int M4P   = 768;   // L4 M (=SEQ) padded to multiple of 128

// ---------------- device scratch ----------------
__device__ __align__(16) float  g_xw[(size_t)SEQ * BATCH];    // [t][b]
__device__ __align__(16) __half g_hs_h[(size_t)SEQ * BATCH];  // [t][b] fp16
// fp16 activations, batch-major [b][k]
__device__ __align__(16) __half g_hsT[(size_t)BATCH * KP_T];
__device__ __align__(16) __half g_a1[(size_t)BATCH * D1];
__device__ __align__(16) __half g_a2[(size_t)BATCH * D2];
__device__ __align__(16) __half g_a3[(size_t)BATCH * D3];
// fp16 split weights, K-major [m][k], zero-padded
__device__ __align__(16) __half g_w1_hi[(size_t)D1 * KP_T];
__device__ __align__(16) __half g_w1_lo[(size_t)D1 * KP_T];
__device__ __align__(16) __half g_w2_hi[(size_t)D2 * D1];
__device__ __align__(16) __half g_w2_lo[(size_t)D2 * D1];
__device__ __align__(16) __half g_w3_hi[(size_t)D3 * D2];
__device__ __align__(16) __half g_w3_lo[(size_t)D3 * D2];
__device__ __align__(16) __half g_w4_hi[(size_t)M4P * D3];
__device__ __align__(16) __half g_w4_lo[(size_t)M4P * D3];

// ---------------- helpers ----------------
__device__ __forceinline__ uint32_t smem_u32(const void* p) {
    uint32_t a;
    asm("{ .reg .u64 t; cvta.to.shared.u64 t, %1; cvt.u32.u64 %0, t; }" : "=r"(a) : "l"(p));
    return a;
}
#define CP_ASYNC16(s, g) \
    asm volatile("cp.async.cg.shared.global [%0], [%1], 16;" :: "r"(s), "l"(g) : "memory")
#define CP_COMMIT() asm volatile("cp.async.commit_group;" ::: "memory")
#define CP_WAIT0()  asm volatile("cp.async.wait_group 0;" ::: "memory")

#define LDSM4(R0, R1, R2, R3, ADDR) \
    asm volatile("ldmatrix.sync.aligned.m8n8.x4.shared.b16 {%0,%1,%2,%3}, [%4];" \
                 : "=r"(R0), "=r"(R1), "=r"(R2), "=r"(R3) : "r"(ADDR))

#define MMA_F16(D, A, B0, B1) \
    asm volatile("mma.sync.aligned.m16n8k16.row.col.f32.f16.f16.f32 " \
                 "{%0,%1,%2,%3}, {%4,%5,%6,%7}, {%8,%9}, {%0,%1,%2,%3};" \
                 : "+f"((D)[0]), "+f"((D)[1]), "+f"((D)[2]), "+f"((D)[3]) \
                 : "r"((A)[0]), "r"((A)[1]), "r"((A)[2]), "r"((A)[3]), \
                   "r"(B0), "r"(B1))

// ---------------------------------------------------------------------------
// Kernel 1: input projection. xw[t][b] = dot(x[b,t,:], W_ih) + b_ih + b_hh
// ---------------------------------------------------------------------------
__global__ __launch_bounds__(256)
void xw_kernel(const float* __restrict__ x,
               const float* __restrict__ W_ih,
               const float* __restrict__ b_ih,
               const float* __restrict__ b_hh,
               float* __restrict__ xw) {
    __shared__ float sx[32 * 225];
    const int b0 = blockIdx.x * 32;
    const int t0 = blockIdx.y * 32;
    const int tid = threadIdx.x;

    for (int e = tid; e < 32 * 224; e += 256) {
        int bb = e / 224, rem = e % 224;
        int t = t0 + rem / 7;
        float v = 0.f;
        if (t < SEQ)
            v = x[((size_t)(b0 + bb) * SEQ + t0) * INP + rem];
        sx[bb * 225 + rem] = v;
    }
    __syncthreads();

    const float w0 = W_ih[0], w1 = W_ih[1], w2 = W_ih[2], w3 = W_ih[3];
    const float w4 = W_ih[4], w5 = W_ih[5], w6 = W_ih[6];
    const float bias = b_ih[0] + b_hh[0];

    for (int e = tid; e < 1024; e += 256) {
        int bb = e % 32, tt = e / 32;
        int t = t0 + tt;
        if (t < SEQ) {
            const float* p = &sx[bb * 225 + tt * 7];
            float s = bias;
            s = fmaf(p[0], w0, s); s = fmaf(p[1], w1, s);
            s = fmaf(p[2], w2, s); s = fmaf(p[3], w3, s);
            s = fmaf(p[4], w4, s); s = fmaf(p[5], w5, s);
            s = fmaf(p[6], w6, s);
            xw[(size_t)t * BATCH + (b0 + bb)] = s;
        }
    }
}

// ---------------------------------------------------------------------------
// Kernel 2: RNN scan (H=1 scalar recurrence), writes fp16 hs
// ---------------------------------------------------------------------------
__global__ __launch_bounds__(128)
void rnn_kernel(const float* __restrict__ xw,
                const float* __restrict__ h0,
                const float* __restrict__ W_hh,
                __half* __restrict__ hs,
                float* __restrict__ hid_out,
                int write_hidden) {
    int b = blockIdx.x * blockDim.x + threadIdx.x;
    if (b >= BATCH) return;
    float h = h0[b];
    const float w = W_hh[0];
    for (int t = 0; t < SEQ; t++) {
        float u = fmaf(w, h, xw[(size_t)t * BATCH + b]);
        float e = __expf(2.f * u);
        h = fmaf(-2.f, __fdividef(1.f, e + 1.f), 1.f);
        hs[(size_t)t * BATCH + b] = __float2half(h);
    }
    if (write_hidden) hid_out[b] = h;
}

// ---------------------------------------------------------------------------
// Kernel 3: transpose hs [t][b] (fp16) -> [b][KP_T] (fp16, zero-padded)
// Consistent 64t x 64b tile through s[64 b][65 t-padded].
// ---------------------------------------------------------------------------
__global__ __launch_bounds__(256)
void transpose_kernel(const __half* __restrict__ hs, __half* __restrict__ hsT) {
    __shared__ __half s[64][65];   // [b][t]
    const int b0 = blockIdx.x * 64, t0 = blockIdx.y * 64;
    const int lx = threadIdx.x & 31, ly = threadIdx.x >> 5;  // ly 0..7
#pragma unroll
    for (int r = 0; r < 8; r++) {
        const int tt = ly + r * 8;          // 0..63
        const int t = t0 + tt;
        __half2 v = __float2half2_rn(0.f);
        if (t < SEQ)
            v = *reinterpret_cast<const __half2*>(hs + (size_t)t * BATCH + b0 + 2 * lx);
        s[2 * lx][tt]     = __low2half(v);
        s[2 * lx + 1][tt] = __high2half(v);
    }
    __syncthreads();
#pragma unroll
    for (int r = 0; r < 8; r++) {
        const int brow = ly + r * 8;        // 0..63
        __half2 v = __halves2half2(s[brow][2 * lx], s[brow][2 * lx + 1]);
        *reinterpret_cast<__half2*>(hsT + (size_t)(b0 + brow) * KP_T + t0 + 2 * lx) = v;
    }
}

// ---------------------------------------------------------------------------
// Kernel 4: all weight splits in ONE launch. 4096 elems per block.
// ---------------------------------------------------------------------------
__device__ __forceinline__ void split_seg(const float* __restrict__ src,
                                          int Mv, int Kv, int Kp,
                                          __half* __restrict__ hi,
                                          __half* __restrict__ lo, int blk) {
    const int base = blk * 4096;
#pragma unroll
    for (int i = 0; i < 16; i++) {
        int idx = base + threadIdx.x + i * 256;
        int r = idx / Kp, c = idx % Kp;
        float v = (r < Mv && c < Kv) ? src[(size_t)r * Kv + c] : 0.f;
        __half h = __float2half(v);
        hi[idx] = h;
        lo[idx] = __float2half(v - __half2float(h));
    }
}

static constexpr int SPLIT_B1 = (D1 * KP_T) / 4096;  // 176
static constexpr int SPLIT_B2 = (D2 * D1) / 4096;    // 128
static constexpr int SPLIT_B3 = (D3 * D2) / 4096;    // 16
static constexpr int SPLIT_B4 = (M4P * D3) / 4096;   // 24
static constexpr int SPLIT_BLOCKS = SPLIT_B1 + SPLIT_B2 + SPLIT_B3 + SPLIT_B4;

__global__ __launch_bounds__(256)
void weight_split_kernel(const float* __restrict__ w1, const float* __restrict__ w2,
                         const float* __restrict__ w3, const float* __restrict__ w4,
                         __half* w1h, __half* w1l, __half* w2h, __half* w2l,
                         __half* w3h, __half* w3l, __half* w4h, __half* w4l) {
    int blk = blockIdx.x;
    if (blk < SPLIT_B1) { split_seg(w1, D1, SEQ, KP_T, w1h, w1l, blk); return; }
    blk -= SPLIT_B1;
    if (blk < SPLIT_B2) { split_seg(w2, D2, D1, D1, w2h, w2l, blk); return; }
    blk -= SPLIT_B2;
    if (blk < SPLIT_B3) { split_seg(w3, D3, D2, D2, w3h, w3l, blk); return; }
    blk -= SPLIT_B3;
    split_seg(w4, SEQ, D3, D3, w4h, w4l, blk);
}

// ---------------------------------------------------------------------------
// Kernel 5: HMMA fp16 GEMM, weights hi/lo 2-pass, 2-stage cp.async pipeline.
//   C[m][n] = sum_k (Ahi+Alo)[m][k] * B[n][k] + bias[m]
//   BM = WM*32, BN = 128. 256 threads, warp tile 32m x (NI*8)n.
//   __launch_bounds__(256, 2) -> 2 CTAs/SM (16 warps) for latency hiding.
//   SMEM row stride 40 halves (80B) -> conflict-free ldmatrix.
// ---------------------------------------------------------------------------
template <int WM, int NI, bool RELU, bool HALF_OUT>
__global__ __launch_bounds__(256, 2)
void mma_gemm_kernel(const __half* __restrict__ Ahi, const __half* __restrict__ Alo,
                     const __half* __restrict__ B,
                     const float* __restrict__ bias,
                     __half* __restrict__ Ch, float* __restrict__ Cf,
                     int Kpad, int Dout, int Mvalid) {
    constexpr int BM = WM * 32;
    constexpr int WN = 8 / WM;
    static_assert(WN * NI * 8 == 128, "BN must be 128");
    constexpr uint32_t T_AL  = BM * 80;
    constexpr uint32_t T_B   = 2 * BM * 80;
    constexpr uint32_t STAGE = (2 * BM + 128) * 80;

    extern __shared__ __align__(16) char smem[];
    const int tid  = threadIdx.x;
    const int lane = tid & 31;
    const int wid  = tid >> 5;
    const int m0 = blockIdx.y * BM;
    const int n0 = blockIdx.x * 128;
    const int m_base = (wid % WM) * 32;
    const int n_base = (wid / WM) * (NI * 8);
    const uint32_t sbase = smem_u32(smem);

    const __half* gAh = Ahi + (size_t)m0 * Kpad;
    const __half* gAl = Alo + (size_t)m0 * Kpad;
    const __half* gB  = B   + (size_t)n0 * Kpad;

    float acc[2][NI][4];
#pragma unroll
    for (int mi = 0; mi < 2; mi++)
#pragma unroll
        for (int ni = 0; ni < NI; ni++)
#pragma unroll
            for (int v = 0; v < 4; v++) acc[mi][ni][v] = 0.f;

    const int stages = Kpad >> 5;

    auto load_stage = [&](int s, int buf) {
        const uint32_t sb = sbase + buf * STAGE;
        const int kofs = s << 5;
#pragma unroll
        for (int c = tid; c < BM * 4; c += 256) {
            const int rr = c >> 2, cc = c & 3;
            const uint32_t so = rr * 80 + cc * 16;
            const size_t go = (size_t)rr * Kpad + kofs + cc * 8;
            CP_ASYNC16(sb + so, gAh + go);
            CP_ASYNC16(sb + T_AL + so, gAl + go);
        }
#pragma unroll
        for (int c = tid; c < 512; c += 256) {
            const int rr = c >> 2, cc = c & 3;
            const uint32_t so = rr * 80 + cc * 16;
            const size_t go = (size_t)rr * Kpad + kofs + cc * 8;
            CP_ASYNC16(sb + T_B + so, gB + go);
        }
    };

    load_stage(0, 0);
    CP_COMMIT();

    for (int s = 0; s < stages; s++) {
        CP_WAIT0();
        __syncthreads();
        if (s + 1 < stages) { load_stage(s + 1, (s + 1) & 1); CP_COMMIT(); }
        const uint32_t sb = sbase + (s & 1) * STAGE;

#pragma unroll
        for (int step = 0; step < 2; step++) {
            const uint32_t kb = step * 32;
            uint32_t ah[2][4], al[2][4], b[NI][2];
            const uint32_t arow = (uint32_t)(m_base + (lane & 15)) * 80 + kb + (lane >> 4) * 16;
#pragma unroll
            for (int mi = 0; mi < 2; mi++) {
                const uint32_t ad = sb + arow + mi * (16 * 80);
                LDSM4(ah[mi][0], ah[mi][1], ah[mi][2], ah[mi][3], ad);
                LDSM4(al[mi][0], al[mi][1], al[mi][2], al[mi][3], ad + T_AL);
            }
            const uint32_t brow = (uint32_t)(n_base + (lane & 15)) * 80 + kb + (lane >> 4) * 16;
#pragma unroll
            for (int g = 0; g < NI / 2; g++) {
                uint32_t t0, t1, t2, t3;
                LDSM4(t0, t1, t2, t3, sb + T_B + brow + g * (16 * 80));
                b[2 * g][0] = t0; b[2 * g][1] = t2;
                b[2 * g + 1][0] = t1; b[2 * g + 1][1] = t3;
            }
            // pass 1: A_hi * B
#pragma unroll
            for (int mi = 0; mi < 2; mi++)
#pragma unroll
                for (int ni = 0; ni < NI; ni++)
                    MMA_F16(acc[mi][ni], ah[mi], b[ni][0], b[ni][1]);
            // pass 2: A_lo * B
#pragma unroll
            for (int mi = 0; mi < 2; mi++)
#pragma unroll
                for (int ni = 0; ni < NI; ni++)
                    MMA_F16(acc[mi][ni], al[mi], b[ni][0], b[ni][1]);
        }
    }

    // epilogue
    const int erow = lane >> 2;
    const int ecol = (lane & 3) * 2;
#pragma unroll
    for (int mi = 0; mi < 2; mi++) {
        const int mA = m0 + m_base + mi * 16 + erow;
        const int mB = mA + 8;
        const bool vA = mA < Mvalid, vB = mB < Mvalid;
        const float bA = vA ? bias[mA] : 0.f;
        const float bB = vB ? bias[mB] : 0.f;
#pragma unroll
        for (int ni = 0; ni < NI; ni++) {
            const int n = n0 + n_base + ni * 8 + ecol;
            float v00 = acc[mi][ni][0] + bA;
            float v01 = acc[mi][ni][1] + bA;
            float v10 = acc[mi][ni][2] + bB;
            float v11 = acc[mi][ni][3] + bB;
            if (RELU) {
                v00 = fmaxf(v00, 0.f); v01 = fmaxf(v01, 0.f);
                v10 = fmaxf(v10, 0.f); v11 = fmaxf(v11, 0.f);
            }
            if constexpr (HALF_OUT) {
                if (vA) {
                    Ch[(size_t)n * Dout + mA] = __float2half(v00);
                    Ch[(size_t)(n + 1) * Dout + mA] = __float2half(v01);
                }
                if (vB) {
                    Ch[(size_t)n * Dout + mB] = __float2half(v10);
                    Ch[(size_t)(n + 1) * Dout + mB] = __float2half(v11);
                }
            } else {
                if (vA) {
                    Cf[(size_t)n * Dout + mA] = v00;
                    Cf[(size_t)(n + 1) * Dout + mA] = v01;
                }
                if (vB) {
                    Cf[(size_t)n * Dout + mB] = v10;
                    Cf[(size_t)(n + 1) * Dout + mB] = v11;
                }
            }
        }
    }
}

// SMEM sizes per config (2 stages, Ahi+Alo+B tiles); 2 CTAs/SM
static constexpr int SMEM_A = 2 * (2 * 128 + 128) * 80;  // WM=4: 61440
static constexpr int SMEM_B = 2 * (2 * 64 + 128) * 80;   // WM=2: 40960

// ---------------------------------------------------------------------------
// Launch
// ---------------------------------------------------------------------------
extern "C" void kernel_launch(void* const* d_in, const int* in_sizes, int n_in,
                              void* d_out, int out_size) {
    const float* x    = (const float*)d_in[0];
    const float* h0   = (const float*)d_in[1];
    const float* W_ih = (const float*)d_in[2];
    const float* W_hh = (const float*)d_in[3];
    const float* b_ih = (const float*)d_in[4];
    const float* b_hh = (const float*)d_in[5];
    const float* w1   = (const float*)d_in[6];
    const float* b1   = (const float*)d_in[7];
    const float* w2   = (const float*)d_in[8];
    const float* b2   = (const float*)d_in[9];
    const float* w3   = (const float*)d_in[10];
    const float* b3   = (const float*)d_in[11];
    const float* w4   = (const float*)d_in[12];
    const float* b4   = (const float*)d_in[13];
    float* out = (float*)d_out;

    float *p_xw;
    __half *p_hs, *hsT, *a1, *a2, *a3;
    __half *w1h, *w1l, *w2h, *w2l, *w3h, *w3l, *w4h, *w4l;
    cudaGetSymbolAddress((void**)&p_xw, g_xw);
    cudaGetSymbolAddress((void**)&p_hs, g_hs_h);
    cudaGetSymbolAddress((void**)&hsT, g_hsT);
    cudaGetSymbolAddress((void**)&a1, g_a1);
    cudaGetSymbolAddress((void**)&a2, g_a2);
    cudaGetSymbolAddress((void**)&a3, g_a3);
    cudaGetSymbolAddress((void**)&w1h, g_w1_hi);
    cudaGetSymbolAddress((void**)&w1l, g_w1_lo);
    cudaGetSymbolAddress((void**)&w2h, g_w2_hi);
    cudaGetSymbolAddress((void**)&w2l, g_w2_lo);
    cudaGetSymbolAddress((void**)&w3h, g_w3_hi);
    cudaGetSymbolAddress((void**)&w3l, g_w3_lo);
    cudaGetSymbolAddress((void**)&w4h, g_w4_hi);
    cudaGetSymbolAddress((void**)&w4l, g_w4_lo);

    cudaFuncSetAttribute(mma_gemm_kernel<4, 8, true, true>,
                         cudaFuncAttributeMaxDynamicSharedMemorySize, SMEM_A);
    cudaFuncSetAttribute(mma_gemm_kernel<2, 4, true, true>,
                         cudaFuncAttributeMaxDynamicSharedMemorySize, SMEM_B);
    cudaFuncSetAttribute(mma_gemm_kernel<4, 8, false, false>,
                         cudaFuncAttributeMaxDynamicSharedMemorySize, SMEM_A);

    const size_t out_elems = (size_t)BATCH * SEQ;
    const int write_hidden = ((size_t)out_size >= out_elems + BATCH) ? 1 : 0;
    float* hid_out = out + out_elems;

    // Weight conversion: single launch
    weight_split_kernel<<<SPLIT_BLOCKS, 256>>>(w1, w2, w3, w4,
                                               w1h, w1l, w2h, w2l,
                                               w3h, w3l, w4h, w4l);

    // Input projection -> g_xw [t][b]
    {
        dim3 grid(BATCH / 32, (SEQ + 31) / 32);
        xw_kernel<<<grid, 256>>>(x, W_ih, b_ih, b_hh, p_xw);
    }
    // RNN scan -> fp16 hs [t][b], hidden tail fp32
    rnn_kernel<<<BATCH / 128, 128>>>(p_xw, h0, W_hh, p_hs, hid_out, write_hidden);

    // Transpose -> hsT [b][KP_T]
    {
        dim3 grid(BATCH / 64, KP_T / 64);
        transpose_kernel<<<grid, 256>>>(p_hs, hsT);
    }

    // L1: a1[b][D1] = relu(w1 . hs + b1)
    {
        dim3 grid(BATCH / 128, D1 / 128);
        mma_gemm_kernel<4, 8, true, true><<<grid, 256, SMEM_A>>>(
            w1h, w1l, hsT, b1, a1, nullptr, KP_T, D1, D1);
    }
    // L2: a2[b][D2] = relu(w2 . a1 + b2)
    {
        dim3 grid(BATCH / 128, D2 / 128);
        mma_gemm_kernel<4, 8, true, true><<<grid, 256, SMEM_A>>>(
            w2h, w2l, a1, b2, a2, nullptr, D1, D2, D2);
    }
    // L3: a3[b][D3] = relu(w3 . a2 + b3)   (BM=64 config -> 128 CTAs)
    {
        dim3 grid(BATCH / 128, D3 / 64);
        mma_gemm_kernel<2, 4, true, true><<<grid, 256, SMEM_B>>>(
            w3h, w3l, a2, b3, a3, nullptr, D2, D3, D3);
    }
    // L4: out[b][t] = w4 . a3 + b4  (fp32 out, m = t, guard m < SEQ)
    {
        dim3 grid(BATCH / 128, M4P / 128);
        mma_gemm_kernel<4, 8, false, false><<<grid, 256, SMEM_A>>>(
            w4h, w4l, a3, b4, nullptr, out, D3, SEQ, SEQ);
    }
}